// round 17
// baseline (speedup 1.0000x reference)
#include <cuda_runtime.h>

#define BATCHES 8
#define N_PER 8192
#define M_PER 2048
#define C_FEAT 32
#define K 32
#define NCH (3 + C_FEAT)              // 35
#define THREADS 896
#define WARPS (THREADS / 32)          // 28
#define GRID_X 148                    // one CTA per SM, uneven batch split
#define M_TOT (BATCHES * M_PER)              // 16384
#define FEAT_ELEMS ((size_t)M_TOT * NCH * K) // 18350080
#define WS_STRIDE 36                  // 32 slots + trash(32) + pad

// smem word layout:
//  sx [0,8192)  sy [8192,16384)  sz [16384,24576)
//  tiles [24576, +WARPS*1024)   32x32 floats per warp, XOR-swizzled
//  slots [.., +WARPS*WS_STRIDE)
//  qctr  [last]
#define OFF_SY    8192
#define OFF_SZ    16384
#define OFF_TILE  24576
#define OFF_WS    (OFF_TILE + WARPS * 1024)        // 53248
#define OFF_QCTR  (OFF_WS + WARPS * WS_STRIDE)     // 54256
#define SMEM_BYTES ((OFF_QCTR + 4) * 4)            // 217040 B <= 232448 cap

// JAX compares d2 < f32(0.04) = 0.039999999105930328f (NOT 0.2f*0.2f)
#define R2 ((float)(0.2 * 0.2))

__device__ __forceinline__ unsigned long long pack2(float a, float b) {
    unsigned long long r;
    asm("mov.b64 %0, {%1, %2};" : "=l"(r) : "f"(a), "f"(b));
    return r;
}
__device__ __forceinline__ void unpack2(unsigned long long v, float& a, float& b) {
    asm("mov.b64 {%0, %1}, %2;" : "=f"(a), "=f"(b) : "l"(v));
}
__device__ __forceinline__ unsigned long long add2(unsigned long long a, unsigned long long b) {
    unsigned long long r;
    asm("add.rn.f32x2 %0, %1, %2;" : "=l"(r) : "l"(a), "l"(b));
    return r;
}
__device__ __forceinline__ unsigned long long mul2(unsigned long long a, unsigned long long b) {
    unsigned long long r;
    asm("mul.rn.f32x2 %0, %1, %2;" : "=l"(r) : "l"(a), "l"(b));
    return r;
}

// process one preloaded 128-candidate block (ballots + branchless slot assign)
#define PROCESS128(XV, YV, ZV, J0)                                             \
    do {                                                                       \
        const unsigned long long dx0 = add2(pack2((XV).x, (XV).y), nqx);       \
        const unsigned long long dy0 = add2(pack2((YV).x, (YV).y), nqy);       \
        const unsigned long long dz0 = add2(pack2((ZV).x, (ZV).y), nqz);       \
        const unsigned long long s0 =                                          \
            add2(add2(mul2(dx0, dx0), mul2(dy0, dy0)), mul2(dz0, dz0));        \
        const unsigned long long dx1 = add2(pack2((XV).z, (XV).w), nqx);       \
        const unsigned long long dy1 = add2(pack2((YV).z, (YV).w), nqy);       \
        const unsigned long long dz1 = add2(pack2((ZV).z, (ZV).w), nqz);       \
        const unsigned long long s1 =                                          \
            add2(add2(mul2(dx1, dx1), mul2(dy1, dy1)), mul2(dz1, dz1));        \
        float d0, d1, d2_, d3;                                                 \
        unpack2(s0, d0, d1);                                                   \
        unpack2(s1, d2_, d3);                                                  \
        const bool b0 = d0 < R2, b1 = d1 < R2, b2 = d2_ < R2, b3 = d3 < R2;    \
        const unsigned m0 = __ballot_sync(0xffffffffu, b0);                    \
        const unsigned m1 = __ballot_sync(0xffffffffu, b1);                    \
        const unsigned m2 = __ballot_sync(0xffffffffu, b2);                    \
        const unsigned m3 = __ballot_sync(0xffffffffu, b3);                    \
        const int jb = (J0) + 4 * lane;                                        \
        const unsigned long long m01 = ((unsigned long long)m0 << 32) | m1;    \
        const unsigned long long m23 = ((unsigned long long)m2 << 32) | m3;    \
        const int below = __popcll(m01 & lm2) + __popcll(m23 & lm2);           \
        const int pos0 = cnt + below;                                          \
        const int pos1 = pos0 + (b0 ? 1 : 0);                                  \
        const int pos2 = pos1 + (b1 ? 1 : 0);                                  \
        const int pos3 = pos2 + (b2 ? 1 : 0);                                  \
        ws[(b0 && pos0 < K) ? pos0 : 32] = jb + 0;                             \
        ws[(b1 && pos1 < K) ? pos1 : 32] = jb + 1;                             \
        ws[(b2 && pos2 < K) ? pos2 : 32] = jb + 2;                             \
        ws[(b3 && pos3 < K) ? pos3 : 32] = jb + 3;                             \
        cnt += __popcll(m01) + __popcll(m23);                                  \
    } while (0)

__global__ __launch_bounds__(THREADS, 1)
void sqag_kernel(const float* __restrict__ xyz,
                 const float* __restrict__ new_xyz,
                 const float* __restrict__ features,
                 float* __restrict__ out)
{
    extern __shared__ float smem[];
    float* sx = smem;
    float* sy = smem + OFF_SY;
    float* sz = smem + OFF_SZ;
    int*   slots = (int*)(smem + OFF_WS);
    int*   qctr  = (int*)(smem + OFF_QCTR);

    // uneven batch mapping: batch = floor(x*8/148); CTA slice of that batch
    const int batch = (int)(blockIdx.x * BATCHES) / GRID_X;
    const int x0 = (batch * GRID_X + BATCHES - 1) / BATCHES;       // first CTA
    const int x1 = ((batch + 1) * GRID_X + BATCHES - 1) / BATCHES; // last+1
    const int ncta_b = x1 - x0;
    const int r_local = blockIdx.x - x0;
    const int q_start = (int)((long long)r_local * M_PER / ncta_b);
    const int q_end   = (int)((long long)(r_local + 1) * M_PER / ncta_b);
    const int nq = q_end - q_start;

    const int bbase = batch * N_PER;
    const float* bx = xyz + (size_t)bbase * 3;

    if (threadIdx.x == 0) *qctr = 0;

    // Stage this batch's xyz into SMEM as SoA (float4-loadable).
    for (int p = threadIdx.x; p < N_PER; p += THREADS) {
        const float* src = bx + 3 * p;
        sx[p] = src[0];
        sy[p] = src[1];
        sz[p] = src[2];
    }
    __syncthreads();

    const int wid  = threadIdx.x >> 5;
    const int lane = threadIdx.x & 31;
    int*   ws   = slots + wid * WS_STRIDE;   // ws[32] = trash slot
    float* tile = smem + OFF_TILE + wid * 1024;
    const unsigned lanemask_lt = (1u << lane) - 1u;
    const unsigned long long lm2 =
        ((unsigned long long)lanemask_lt << 32) | lanemask_lt;
    const int j4 = lane >> 3;   // 0..3 (row-in-round for gather)
    const int cc = lane & 7;    // 0..7 (float4 chunk within feature row)

    const float4* px4 = (const float4*)(sx + 4 * lane);
    const float4* py4 = (const float4*)(sy + 4 * lane);
    const float4* pz4 = (const float4*)(sz + 4 * lane);

    for (;;) {
        int qt;
        if (lane == 0) qt = atomicAdd(qctr, 1);
        qt = __shfl_sync(0xffffffffu, qt, 0);
        if (qt >= nq) break;

        const int m = batch * M_PER + q_start + qt;
        const float* qp = new_xyz + (size_t)m * 3;
        const float qx = qp[0], qy = qp[1], qz = qp[2];
        // packed (-q,-q): x + (-q) is bit-identical to x - q (IEEE rn)
        const unsigned long long nqx = pack2(-qx, -qx);
        const unsigned long long nqy = pack2(-qy, -qy);
        const unsigned long long nqz = pack2(-qz, -qz);

        // ---- scan: exit check every 256 candidates; all 6 loads up front
        int cnt = 0;  // warp-uniform
        for (int j0 = 0; j0 < N_PER && cnt < K; j0 += 256) {
            const int o  = j0 >> 2;
            const float4 xvA = px4[o];
            const float4 yvA = py4[o];
            const float4 zvA = pz4[o];
            const float4 xvB = px4[o + 32];
            const float4 yvB = py4[o + 32];
            const float4 zvB = pz4[o + 32];

            PROCESS128(xvA, yvA, zvA, j0);
            PROCESS128(xvB, yvB, zvB, j0 + 128);
        }
        __syncwarp();

        const bool empty = (cnt == 0);
        const int c = cnt < K ? cnt : K;
        const float sc = empty ? 0.0f : 1.0f;

        // branchless: address-select, single LDS, then empty-mask
        int i = ws[(lane < c) ? lane : 0];
        i = empty ? 0 : i;

        // ---- feature gather via cp.async: global -> swizzled tile, no regs
        #pragma unroll
        for (int r = 0; r < 8; r++) {
            const int s  = 4 * r + j4;
            const int is = __shfl_sync(0xffffffffu, i, s);
            const float* src = features + (size_t)(bbase + is) * C_FEAT + 4 * cc;
            const unsigned dst = (unsigned)__cvta_generic_to_shared(
                tile + s * 32 + ((4 * cc) ^ (4 * (s & 7))));
            asm volatile("cp.async.ca.shared.global [%0], [%1], 16;\n"
                         :: "r"(dst), "l"(src));
        }
        asm volatile("cp.async.commit_group;\n" ::: "memory");

        // ---- xyz channels (lane = k) — overlaps with cp.async in flight
        const float px = sx[i], py = sy[i], pz = sz[i];
        const size_t ob = (size_t)m * (NCH * K);
        out[ob + 0 * K + lane] = (px - qx) * sc;
        out[ob + 1 * K + lane] = (py - qy) * sc;
        out[ob + 2 * K + lane] = (pz - qz) * sc;

        // Output dtype is float32: idx stored as float (0..8191 exact).
        out[FEAT_ELEMS + (size_t)m * K + lane] = empty ? 0.0f : (float)i;

        asm volatile("cp.async.wait_group 0;\n" ::: "memory");
        __syncwarp();

        // ---- feature channels: lane k reads its tile row (LDS.128);
        //      sc multiply applied at readout (empty-query zeroing)
        const float* trow = tile + lane * 32;
        const int txor = 4 * (lane & 7);
        #pragma unroll
        for (int t = 0; t < 8; t++) {
            const float4 v = *(const float4*)(trow + ((4 * t) ^ txor));
            out[ob + (size_t)(3 + 4 * t + 0) * K + lane] = v.x * sc;
            out[ob + (size_t)(3 + 4 * t + 1) * K + lane] = v.y * sc;
            out[ob + (size_t)(3 + 4 * t + 2) * K + lane] = v.z * sc;
            out[ob + (size_t)(3 + 4 * t + 3) * K + lane] = v.w * sc;
        }
        __syncwarp();
    }
}

extern "C" void kernel_launch(void* const* d_in, const int* in_sizes, int n_in,
                              void* d_out, int out_size)
{
    const float* xyz      = (const float*)d_in[0];
    // d_in[1]: xyz_batch_cnt (constant N_PER, unused)
    const float* new_xyz  = (const float*)d_in[2];
    // d_in[3]: new_xyz_batch_cnt (constant M_PER, unused)
    const float* features = (const float*)d_in[4];

    cudaFuncSetAttribute(sqag_kernel,
                         cudaFuncAttributeMaxDynamicSharedMemorySize, SMEM_BYTES);

    sqag_kernel<<<GRID_X, THREADS, SMEM_BYTES>>>(xyz, new_xyz, features,
                                                 (float*)d_out);
}